// round 8
// baseline (speedup 1.0000x reference)
#include <cuda_runtime.h>
#include <cstdint>

#define NROI      256
#define NCH       256
#define NPTS      7
#define HP        8
#define H0F       200
#define W0F       336
#define IMG_W     1344.0f
#define IMG_H     800.0f
#define CCHUNK    64          // channels per block (two 32-ch interleaved streams)

// ---------------------------------------------------------------------------
// Lane-contiguous pooler, dual-channel-stream version, single fused launch.
//
// - lane = one output x (warp covers 32 consecutive x) -> warp gather
//   footprint is ~2-3 cache lines per tap (L1 wavefront minimal).
// - CCHUNK=64 channels per block as TWO interleaved streams (c, c+32):
//   8 independent LDGs per loop iteration; unroll 4 -> 32-load window.
//   Halves block count (3072) => half the per-block preamble cost.
// - No smem/barriers: ROI meta recomputed per thread from broadcast __ldg.
// - __stcs evict-first stores (output is write-once; keep L2 for gathers).
//
// Grid (12, NROI):
//   bx in [0,4):   output0 (WP=32): 256 thr = 32 x * 8 y, chunk = bx
//   bx in [4,12):  output1 (WP=64): 256 thr = 64 x * 4 y, idx = bx-4,
//                  chunk = idx>>1, y-half = idx&1
// ---------------------------------------------------------------------------

template <int WP, int PID, int YROWS>
__device__ __forceinline__ void pool_body(
    int chunk, int yblk, int n,
    const float* __restrict__ f0, const float* __restrict__ f1,
    const float* __restrict__ f2, const float* __restrict__ f3,
    float* __restrict__ outp, const float* __restrict__ pp,
    int s_lvl, int s_pid, int s_img) {

    const int x  = threadIdx.x % WP;
    const int y  = yblk * YROWS + threadIdx.x / WP;
    const int c0 = chunk * CCHUNK;

    if (s_pid != PID) {
        // Zero region: CCHUNK ch x YROWS x WP = 16384 floats = 4096 float4.
        constexpr int F4_PER_CH = YROWS * WP / 4;   // 64
        const float4 z = make_float4(0.f, 0.f, 0.f, 0.f);
#pragma unroll
        for (int t = 0; t < CCHUNK * F4_PER_CH / 256; t++) {   // 16
            int idx = t * 256 + threadIdx.x;
            int c   = idx / F4_PER_CH;
            int off = idx % F4_PER_CH;
            float4* zp = (float4*)(outp +
                (((size_t)n * NCH + c0 + c) * HP + yblk * YROWS) * WP) + off;
            __stcs(zp, z);
        }
        return;
    }

    int H, W;
    const float* feat;
    switch (s_lvl) {
        case 0:  H = H0F;     W = W0F;     feat = f0; break;
        case 1:  H = H0F / 2; W = W0F / 2; feat = f1; break;
        case 2:  H = H0F / 4; W = W0F / 4; feat = f2; break;
        default: H = H0F / 8; W = W0F / 8; feat = f3; break;
    }
    const size_t HW = (size_t)H * W;
    const float* pA = feat + ((size_t)s_img * NCH + c0) * HW;
    const float* pB = pA + (size_t)(CCHUNK / 2) * HW;
    float* op = outp + (((size_t)n * NCH + c0) * HP + y) * WP + x;

    // --- per-thread grid sample (once) ---
    const float v    = (y + 0.5f) * (1.0f / HP);
    const float invW = 1.0f / IMG_W, invH = 1.0f / IMG_H;

    float u = (x + 0.5f) * ((float)(NPTS - 1) / (float)WP);
    int i0 = (int)floorf(u);
    i0 = max(0, min(i0, NPTS - 2));
    float f = u - (float)i0;
    int j0 = 13 - i0, j1 = 12 - i0;

    float tx = (__ldg(pp + 2*i0)     * (1.0f - f) + __ldg(pp + 2*(i0+1))     * f) * invW;
    float ty = (__ldg(pp + 2*i0 + 1) * (1.0f - f) + __ldg(pp + 2*(i0+1) + 1) * f) * invH;
    float bx = (__ldg(pp + 2*j0)     * (1.0f - f) + __ldg(pp + 2*j1)         * f) * invW;
    float by = (__ldg(pp + 2*j0 + 1) * (1.0f - f) + __ldg(pp + 2*j1 + 1)     * f) * invH;

    float gx = tx * (1.0f - v) + bx * v;
    float gy = ty * (1.0f - v) + by * v;

    float xf = gx * (float)W - 0.5f;
    float yf = gy * (float)H - 0.5f;
    float x0f = floorf(xf), y0f = floorf(yf);
    float wx = xf - x0f, wy = yf - y0f;
    int x0 = (int)x0f, y0i = (int)y0f;
    int x1 = x0 + 1,   y1 = y0i + 1;

    int x0c = min(max(x0, 0), W - 1), x1c = min(max(x1, 0), W - 1);
    int y0c = min(max(y0i, 0), H - 1), y1c = min(max(y1, 0), H - 1);
    float m00 = ((x0 >= 0) & (x0 < W) & (y0i >= 0) & (y0i < H)) ? 1.0f : 0.0f;
    float m10 = ((x1 >= 0) & (x1 < W) & (y0i >= 0) & (y0i < H)) ? 1.0f : 0.0f;
    float m01 = ((x0 >= 0) & (x0 < W) & (y1 >= 0) & (y1 < H)) ? 1.0f : 0.0f;
    float m11 = ((x1 >= 0) & (x1 < W) & (y1 >= 0) & (y1 < H)) ? 1.0f : 0.0f;

    const float w00 = m00 * (1.0f - wx) * (1.0f - wy);
    const float w10 = m10 * wx          * (1.0f - wy);
    const float w01 = m01 * (1.0f - wx) * wy;
    const float w11 = m11 * wx          * wy;

    const int o00 = y0c * W + x0c;
    const int o10 = y0c * W + x1c;
    const int o01 = y1c * W + x0c;
    const int o11 = y1c * W + x1c;

    constexpr size_t OST  = (size_t)HP * WP;               // out channel stride
    float* opB = op + (size_t)(CCHUNK / 2) * OST;

    // --- dual channel streams: 8 independent LDGs per iter, unroll 4 ---
#pragma unroll 4
    for (int c = 0; c < CCHUNK / 2; c++) {
        float a00 = __ldg(pA + o00);
        float a10 = __ldg(pA + o10);
        float a01 = __ldg(pA + o01);
        float a11 = __ldg(pA + o11);
        float b00 = __ldg(pB + o00);
        float b10 = __ldg(pB + o10);
        float b01 = __ldg(pB + o01);
        float b11 = __ldg(pB + o11);
        float ra = a00 * w00 + a10 * w10 + a01 * w01 + a11 * w11;
        float rb = b00 * w00 + b10 * w10 + b01 * w01 + b11 * w11;
        __stcs(op  + (size_t)c * OST, ra);
        __stcs(opB + (size_t)c * OST, rb);
        pA += HW;
        pB += HW;
    }
}

__global__ void __launch_bounds__(256, 4)
fused_pool_kernel(const float* __restrict__ f0, const float* __restrict__ f1,
                  const float* __restrict__ f2, const float* __restrict__ f3,
                  const float* __restrict__ polys, const int* __restrict__ img_ids,
                  const int* __restrict__ lens, float* __restrict__ out) {
    const int n = blockIdx.y;
    const float* pp = polys + (size_t)n * (2 * NPTS * 2);

    // --- per-thread uniform meta (broadcast __ldg; no smem, no barriers) ---
    float minx = __ldg(pp + 0), maxx = minx;
    float miny = __ldg(pp + 1), maxy = miny;
#pragma unroll
    for (int i = 1; i < 2 * NPTS; i++) {
        float px = __ldg(pp + 2 * i), py = __ldg(pp + 2 * i + 1);
        minx = fminf(minx, px); maxx = fmaxf(maxx, px);
        miny = fminf(miny, py); maxy = fmaxf(maxy, py);
    }
    float s  = sqrtf((maxx - minx) * (maxy - miny));
    float vv = 4.0f + log2f(s / 224.0f + 1e-6f);
    float fl = fminf(fmaxf(floorf(vv), 2.0f), 5.0f);
    const int s_lvl = (int)fl - 2;
    const int s_pid = (__ldg(lens + n) > 8) ? 1 : 0;
    const int s_img = __ldg(img_ids + n);

    constexpr int CHUNKS = NCH / CCHUNK;   // 4

    if (blockIdx.x < CHUNKS) {
        // Output 0: (N, C, 8, 32), pooler 0. 256 thr = 32 x * 8 y.
        pool_body<32, 0, 8>(blockIdx.x, 0, n, f0, f1, f2, f3,
                            out, pp, s_lvl, s_pid, s_img);
    } else {
        // Output 1: (N, C, 8, 64), pooler 1. 256 thr = 64 x * 4 y, 2 halves.
        const int idx = blockIdx.x - CHUNKS;
        float* out1 = out + (size_t)NROI * NCH * HP * 32;
        pool_body<64, 1, 4>(idx >> 1, idx & 1, n, f0, f1, f2, f3,
                            out1, pp, s_lvl, s_pid, s_img);
    }
}

extern "C" void kernel_launch(void* const* d_in, const int* in_sizes, int n_in,
                              void* d_out, int out_size) {
    const float* f0     = (const float*)d_in[0];
    const float* f1     = (const float*)d_in[1];
    const float* f2     = (const float*)d_in[2];
    const float* f3     = (const float*)d_in[3];
    const float* polys  = (const float*)d_in[4];
    const int*   imgids = (const int*)  d_in[5];
    const int*   lens   = (const int*)  d_in[6];
    float* out = (float*)d_out;

    const int N = in_sizes[4] / (2 * NPTS * 2);   // 256

    dim3 grid(3 * (NCH / CCHUNK), N);             // 12 x 256
    fused_pool_kernel<<<grid, 256>>>(f0, f1, f2, f3, polys, imgids, lens, out);
}

// round 9
// speedup vs baseline: 2.2079x; 2.2079x over previous
#include <cuda_runtime.h>
#include <cstdint>

#define NROI      256
#define NCH       256
#define NPTS      7
#define HP        8
#define H0F       200
#define W0F       336
#define IMG_W     1344.0f
#define IMG_H     800.0f
#define CCHUNK    64          // channels per block (single stream; R7 inner loop)

// ---------------------------------------------------------------------------
// Lane-contiguous pooler. R7's proven inner loop (single channel stream,
// 4 LDG + 1 STG per channel, unroll 8 => 16-load window, fits 48 regs at
// occupancy 5), with CCHUNK doubled to 64 to halve block count (3072):
// half the per-block preamble cost and wave-transition overhead.
//
// - lane = one output x (warp covers 32 consecutive x) -> warp gather
//   footprint ~2-5 cache lines per tap.
// - No smem/barriers: ROI meta recomputed per thread from broadcast __ldg.
// - __stcs evict-first on all output stores (write-once data).
//
// Grid (12, NROI):
//   bx in [0,4):   output0 (WP=32): 256 thr = 32 x * 8 y, chunk = bx
//   bx in [4,12):  output1 (WP=64): 256 thr = 64 x * 4 y, idx = bx-4,
//                  chunk = idx>>1, y-half = idx&1
// ---------------------------------------------------------------------------

template <int WP, int PID, int YROWS>
__device__ __forceinline__ void pool_body(
    int chunk, int yblk, int n,
    const float* __restrict__ f0, const float* __restrict__ f1,
    const float* __restrict__ f2, const float* __restrict__ f3,
    float* __restrict__ outp, const float* __restrict__ pp,
    int s_lvl, int s_pid, int s_img) {

    const int x  = threadIdx.x % WP;
    const int y  = yblk * YROWS + threadIdx.x / WP;
    const int c0 = chunk * CCHUNK;

    if (s_pid != PID) {
        // Zero region: CCHUNK ch x YROWS x WP = 16384 floats = 4096 float4.
        constexpr int F4_PER_CH = YROWS * WP / 4;   // 64
        const float4 z = make_float4(0.f, 0.f, 0.f, 0.f);
#pragma unroll
        for (int t = 0; t < CCHUNK * F4_PER_CH / 256; t++) {   // 16
            int idx = t * 256 + threadIdx.x;
            int c   = idx / F4_PER_CH;
            int off = idx % F4_PER_CH;
            float4* zp = (float4*)(outp +
                (((size_t)n * NCH + c0 + c) * HP + yblk * YROWS) * WP) + off;
            __stcs(zp, z);
        }
        return;
    }

    int H, W;
    const float* feat;
    switch (s_lvl) {
        case 0:  H = H0F;     W = W0F;     feat = f0; break;
        case 1:  H = H0F / 2; W = W0F / 2; feat = f1; break;
        case 2:  H = H0F / 4; W = W0F / 4; feat = f2; break;
        default: H = H0F / 8; W = W0F / 8; feat = f3; break;
    }
    const size_t HW = (size_t)H * W;
    const float* p = feat + ((size_t)s_img * NCH + c0) * HW;
    float* op = outp + (((size_t)n * NCH + c0) * HP + y) * WP + x;

    // --- per-thread grid sample (once) ---
    const float v    = (y + 0.5f) * (1.0f / HP);
    const float invW = 1.0f / IMG_W, invH = 1.0f / IMG_H;

    float u = (x + 0.5f) * ((float)(NPTS - 1) / (float)WP);
    int i0 = (int)floorf(u);
    i0 = max(0, min(i0, NPTS - 2));
    float f = u - (float)i0;
    int j0 = 13 - i0, j1 = 12 - i0;

    float tx = (__ldg(pp + 2*i0)     * (1.0f - f) + __ldg(pp + 2*(i0+1))     * f) * invW;
    float ty = (__ldg(pp + 2*i0 + 1) * (1.0f - f) + __ldg(pp + 2*(i0+1) + 1) * f) * invH;
    float bx = (__ldg(pp + 2*j0)     * (1.0f - f) + __ldg(pp + 2*j1)         * f) * invW;
    float by = (__ldg(pp + 2*j0 + 1) * (1.0f - f) + __ldg(pp + 2*j1 + 1)     * f) * invH;

    float gx = tx * (1.0f - v) + bx * v;
    float gy = ty * (1.0f - v) + by * v;

    float xf = gx * (float)W - 0.5f;
    float yf = gy * (float)H - 0.5f;
    float x0f = floorf(xf), y0f = floorf(yf);
    float wx = xf - x0f, wy = yf - y0f;
    int x0 = (int)x0f, y0i = (int)y0f;
    int x1 = x0 + 1,   y1 = y0i + 1;

    int x0c = min(max(x0, 0), W - 1), x1c = min(max(x1, 0), W - 1);
    int y0c = min(max(y0i, 0), H - 1), y1c = min(max(y1, 0), H - 1);
    float m00 = ((x0 >= 0) & (x0 < W) & (y0i >= 0) & (y0i < H)) ? 1.0f : 0.0f;
    float m10 = ((x1 >= 0) & (x1 < W) & (y0i >= 0) & (y0i < H)) ? 1.0f : 0.0f;
    float m01 = ((x0 >= 0) & (x0 < W) & (y1 >= 0) & (y1 < H)) ? 1.0f : 0.0f;
    float m11 = ((x1 >= 0) & (x1 < W) & (y1 >= 0) & (y1 < H)) ? 1.0f : 0.0f;

    const float w00 = m00 * (1.0f - wx) * (1.0f - wy);
    const float w10 = m10 * wx          * (1.0f - wy);
    const float w01 = m01 * (1.0f - wx) * wy;
    const float w11 = m11 * wx          * wy;

    const int o00 = y0c * W + x0c;
    const int o10 = y0c * W + x1c;
    const int o01 = y1c * W + x0c;
    const int o11 = y1c * W + x1c;

    constexpr size_t OST = (size_t)HP * WP;   // output channel stride

    // --- channel stream: 4 LDG + 1 STG per channel, unroll 8 (R7-proven) ---
#pragma unroll 8
    for (int c = 0; c < CCHUNK; c++) {
        float v00 = __ldg(p + o00);
        float v10 = __ldg(p + o10);
        float v01 = __ldg(p + o01);
        float v11 = __ldg(p + o11);
        float r = v00 * w00 + v10 * w10 + v01 * w01 + v11 * w11;
        __stcs(op + (size_t)c * OST, r);
        p += HW;
    }
}

__global__ void __launch_bounds__(256, 5)
fused_pool_kernel(const float* __restrict__ f0, const float* __restrict__ f1,
                  const float* __restrict__ f2, const float* __restrict__ f3,
                  const float* __restrict__ polys, const int* __restrict__ img_ids,
                  const int* __restrict__ lens, float* __restrict__ out) {
    const int n = blockIdx.y;
    const float* pp = polys + (size_t)n * (2 * NPTS * 2);

    // --- per-thread uniform meta (broadcast __ldg; no smem, no barriers) ---
    float minx = __ldg(pp + 0), maxx = minx;
    float miny = __ldg(pp + 1), maxy = miny;
#pragma unroll
    for (int i = 1; i < 2 * NPTS; i++) {
        float px = __ldg(pp + 2 * i), py = __ldg(pp + 2 * i + 1);
        minx = fminf(minx, px); maxx = fmaxf(maxx, px);
        miny = fminf(miny, py); maxy = fmaxf(maxy, py);
    }
    float s  = sqrtf((maxx - minx) * (maxy - miny));
    float vv = 4.0f + log2f(s / 224.0f + 1e-6f);
    float fl = fminf(fmaxf(floorf(vv), 2.0f), 5.0f);
    const int s_lvl = (int)fl - 2;
    const int s_pid = (__ldg(lens + n) > 8) ? 1 : 0;
    const int s_img = __ldg(img_ids + n);

    constexpr int CHUNKS = NCH / CCHUNK;   // 4

    if (blockIdx.x < CHUNKS) {
        // Output 0: (N, C, 8, 32), pooler 0. 256 thr = 32 x * 8 y.
        pool_body<32, 0, 8>(blockIdx.x, 0, n, f0, f1, f2, f3,
                            out, pp, s_lvl, s_pid, s_img);
    } else {
        // Output 1: (N, C, 8, 64), pooler 1. 256 thr = 64 x * 4 y, 2 halves.
        const int idx = blockIdx.x - CHUNKS;
        float* out1 = out + (size_t)NROI * NCH * HP * 32;
        pool_body<64, 1, 4>(idx >> 1, idx & 1, n, f0, f1, f2, f3,
                            out1, pp, s_lvl, s_pid, s_img);
    }
}

extern "C" void kernel_launch(void* const* d_in, const int* in_sizes, int n_in,
                              void* d_out, int out_size) {
    const float* f0     = (const float*)d_in[0];
    const float* f1     = (const float*)d_in[1];
    const float* f2     = (const float*)d_in[2];
    const float* f3     = (const float*)d_in[3];
    const float* polys  = (const float*)d_in[4];
    const int*   imgids = (const int*)  d_in[5];
    const int*   lens   = (const int*)  d_in[6];
    float* out = (float*)d_out;

    const int N = in_sizes[4] / (2 * NPTS * 2);   // 256

    dim3 grid(3 * (NCH / CCHUNK), N);             // 12 x 256
    fused_pool_kernel<<<grid, 256>>>(f0, f1, f2, f3, polys, imgids, lens, out);
}

// round 10
// speedup vs baseline: 2.2641x; 1.0255x over previous
#include <cuda_runtime.h>
#include <cstdint>

#define NROI      256
#define NCH       256
#define NPTS      7
#define HP        8
#define H0F       200
#define W0F       336
#define IMG_W     1344.0f
#define IMG_H     800.0f

// ---------------------------------------------------------------------------
// Fused zero+gather pooler. Grid (8, NROI): each block owns, for its ROI,
//   - out0 chunk:  channels [bx*32, bx*32+32), all 8 y, 32 x
//   - out1 slice:  channels [(bx>>1)*64, +64), y-half (bx&1), 64 x
// The block ZEROS the output its ROI does not match (pure __stcs stream,
// issued first: primes DRAM, no dependencies), then GATHERS the matched
// output with the proven lane-contiguous loop (4 LDG + 1 STG per channel,
// unroll 8, 48-reg budget).
// Every block mixes a store burst with a gather phase -> store traffic
// overlaps gather latency chip-wide; no light-block wave imbalance.
// ---------------------------------------------------------------------------

template <int CCH, int YROWS, int WP>
__device__ __forceinline__ void zero_region(
    float* __restrict__ outp, int n, int c0, int yblk) {
    constexpr int F4_PER_CH = YROWS * WP / 4;
    const float4 z = make_float4(0.f, 0.f, 0.f, 0.f);
#pragma unroll
    for (int t = 0; t < CCH * F4_PER_CH / 256; t++) {
        int idx = t * 256 + threadIdx.x;
        int c   = idx / F4_PER_CH;
        int off = idx % F4_PER_CH;
        float4* zp = (float4*)(outp +
            (((size_t)n * NCH + c0 + c) * HP + yblk * YROWS) * WP) + off;
        __stcs(zp, z);
    }
}

template <int WP, int YROWS, int CCH>
__device__ __forceinline__ void gather_region(
    int c0, int yblk, int n,
    const float* __restrict__ f0, const float* __restrict__ f1,
    const float* __restrict__ f2, const float* __restrict__ f3,
    float* __restrict__ outp, const float* __restrict__ pp,
    int s_lvl, int s_img) {

    const int x = threadIdx.x % WP;
    const int y = yblk * YROWS + threadIdx.x / WP;

    int H, W;
    const float* feat;
    switch (s_lvl) {
        case 0:  H = H0F;     W = W0F;     feat = f0; break;
        case 1:  H = H0F / 2; W = W0F / 2; feat = f1; break;
        case 2:  H = H0F / 4; W = W0F / 4; feat = f2; break;
        default: H = H0F / 8; W = W0F / 8; feat = f3; break;
    }
    const size_t HW = (size_t)H * W;
    const float* p = feat + ((size_t)s_img * NCH + c0) * HW;
    float* op = outp + (((size_t)n * NCH + c0) * HP + y) * WP + x;

    const float v    = (y + 0.5f) * (1.0f / HP);
    const float invW = 1.0f / IMG_W, invH = 1.0f / IMG_H;

    float u = (x + 0.5f) * ((float)(NPTS - 1) / (float)WP);
    int i0 = (int)floorf(u);
    i0 = max(0, min(i0, NPTS - 2));
    float f = u - (float)i0;
    int j0 = 13 - i0, j1 = 12 - i0;

    float tx = (__ldg(pp + 2*i0)     * (1.0f - f) + __ldg(pp + 2*(i0+1))     * f) * invW;
    float ty = (__ldg(pp + 2*i0 + 1) * (1.0f - f) + __ldg(pp + 2*(i0+1) + 1) * f) * invH;
    float bx = (__ldg(pp + 2*j0)     * (1.0f - f) + __ldg(pp + 2*j1)         * f) * invW;
    float by = (__ldg(pp + 2*j0 + 1) * (1.0f - f) + __ldg(pp + 2*j1 + 1)     * f) * invH;

    float gx = tx * (1.0f - v) + bx * v;
    float gy = ty * (1.0f - v) + by * v;

    float xf = gx * (float)W - 0.5f;
    float yf = gy * (float)H - 0.5f;
    float x0f = floorf(xf), y0f = floorf(yf);
    float wx = xf - x0f, wy = yf - y0f;
    int x0 = (int)x0f, y0i = (int)y0f;
    int x1 = x0 + 1,   y1 = y0i + 1;

    int x0c = min(max(x0, 0), W - 1), x1c = min(max(x1, 0), W - 1);
    int y0c = min(max(y0i, 0), H - 1), y1c = min(max(y1, 0), H - 1);
    float m00 = ((x0 >= 0) & (x0 < W) & (y0i >= 0) & (y0i < H)) ? 1.0f : 0.0f;
    float m10 = ((x1 >= 0) & (x1 < W) & (y0i >= 0) & (y0i < H)) ? 1.0f : 0.0f;
    float m01 = ((x0 >= 0) & (x0 < W) & (y1 >= 0) & (y1 < H)) ? 1.0f : 0.0f;
    float m11 = ((x1 >= 0) & (x1 < W) & (y1 >= 0) & (y1 < H)) ? 1.0f : 0.0f;

    const float w00 = m00 * (1.0f - wx) * (1.0f - wy);
    const float w10 = m10 * wx          * (1.0f - wy);
    const float w01 = m01 * (1.0f - wx) * wy;
    const float w11 = m11 * wx          * wy;

    const int o00 = y0c * W + x0c;
    const int o10 = y0c * W + x1c;
    const int o01 = y1c * W + x0c;
    const int o11 = y1c * W + x1c;

    constexpr size_t OST = (size_t)HP * WP;

#pragma unroll 8
    for (int c = 0; c < CCH; c++) {
        float v00 = __ldg(p + o00);
        float v10 = __ldg(p + o10);
        float v01 = __ldg(p + o01);
        float v11 = __ldg(p + o11);
        float r = v00 * w00 + v10 * w10 + v01 * w01 + v11 * w11;
        __stcs(op + (size_t)c * OST, r);
        p += HW;
    }
}

__global__ void __launch_bounds__(256, 5)
fused_pool_kernel(const float* __restrict__ f0, const float* __restrict__ f1,
                  const float* __restrict__ f2, const float* __restrict__ f3,
                  const float* __restrict__ polys, const int* __restrict__ img_ids,
                  const int* __restrict__ lens, float* __restrict__ out) {
    const int n  = blockIdx.y;
    const int bx = blockIdx.x;
    const float* pp = polys + (size_t)n * (2 * NPTS * 2);

    // --- per-thread uniform meta (broadcast __ldg; no smem, no barriers) ---
    float minx = __ldg(pp + 0), maxx = minx;
    float miny = __ldg(pp + 1), maxy = miny;
#pragma unroll
    for (int i = 1; i < 2 * NPTS; i++) {
        float px = __ldg(pp + 2 * i), py = __ldg(pp + 2 * i + 1);
        minx = fminf(minx, px); maxx = fmaxf(maxx, px);
        miny = fminf(miny, py); maxy = fmaxf(maxy, py);
    }
    float s  = sqrtf((maxx - minx) * (maxy - miny));
    float vv = 4.0f + log2f(s / 224.0f + 1e-6f);
    float fl = fminf(fmaxf(floorf(vv), 2.0f), 5.0f);
    const int s_lvl = (int)fl - 2;
    const int s_pid = (__ldg(lens + n) > 8) ? 1 : 0;
    const int s_img = __ldg(img_ids + n);

    float* out1 = out + (size_t)NROI * NCH * HP * 32;

    // This block's portions:
    //   out0: channels [bx*32, +32), yblk 0 (all 8 rows), WP=32
    //   out1: channels [(bx>>1)*64, +64), yblk = bx&1 (4 rows), WP=64
    const int c0_o0 = bx * 32;
    const int c0_o1 = (bx >> 1) * 64;
    const int yb_o1 = bx & 1;

    if (s_pid == 0) {
        // zero mismatched out1 slice first (store burst), then gather out0
        zero_region<64, 4, 64>(out1, n, c0_o1, yb_o1);
        gather_region<32, 8, 32>(c0_o0, 0, n, f0, f1, f2, f3,
                                 out, pp, s_lvl, s_img);
    } else {
        // zero mismatched out0 chunk first, then gather out1 slice
        zero_region<32, 8, 32>(out, n, c0_o0, 0);
        gather_region<64, 4, 64>(c0_o1, yb_o1, n, f0, f1, f2, f3,
                                 out1, pp, s_lvl, s_img);
    }
}

extern "C" void kernel_launch(void* const* d_in, const int* in_sizes, int n_in,
                              void* d_out, int out_size) {
    const float* f0     = (const float*)d_in[0];
    const float* f1     = (const float*)d_in[1];
    const float* f2     = (const float*)d_in[2];
    const float* f3     = (const float*)d_in[3];
    const float* polys  = (const float*)d_in[4];
    const int*   imgids = (const int*)  d_in[5];
    const int*   lens   = (const int*)  d_in[6];
    float* out = (float*)d_out;

    const int N = in_sizes[4] / (2 * NPTS * 2);   // 256

    dim3 grid(8, N);                              // 2048 uniform blocks
    fused_pool_kernel<<<grid, 256>>>(f0, f1, f2, f3, polys, imgids, lens, out);
}